// round 3
// baseline (speedup 1.0000x reference)
#include <cuda_runtime.h>

#define N_NODES 50000
#define N_EDGES 800000

// ---------------- scratch (no allocation allowed) ----------------
__device__ float g_agg[N_NODES * 128];   // aggregation buffer (reused both layers)
__device__ float g_h  [N_NODES * 128];   // layer-1 hidden activations
__device__ float g_cnt[N_NODES];         // in-degree counts (computed once)
__device__ float g_B1 [256 * 128];       // [W1l; W1r]^T  k-major: B1[k][o]
__device__ float g_B2 [256 * 64];        // [W2l; W2r]^T  k-major: B2[k][o]

// ---------------- weight prep: build concatenated k-major B ----------------
__global__ void prep_weights(const float* __restrict__ W1l, const float* __restrict__ W1r,
                             const float* __restrict__ W2l, const float* __restrict__ W2r) {
    int t = blockIdx.x * blockDim.x + threadIdx.x;
    if (t < 256 * 128) {
        int k = t >> 7, o = t & 127;
        g_B1[t] = (k < 128) ? W1l[o * 128 + k] : W1r[o * 128 + (k - 128)];
    }
    int t2 = t - 256 * 128;
    if (t2 >= 0 && t2 < 256 * 64) {
        int k = t2 >> 6, o = t2 & 63;
        g_B2[t2] = (k < 128) ? W2l[o * 128 + k] : W2r[o * 128 + (k - 128)];
    }
}

// ---------------- zero agg (and optionally cnt) ----------------
__global__ void zero_agg_cnt(int zero_cnt) {
    int t = blockIdx.x * blockDim.x + threadIdx.x;
    float4 z = make_float4(0.f, 0.f, 0.f, 0.f);
    if (t < N_NODES * 32) ((float4*)g_agg)[t] = z;
    if (zero_cnt && t < N_NODES) g_cnt[t] = 0.f;
}

// ---------------- degree count (once; graph identical for both layers) -----
__global__ void count_edges(const int* __restrict__ ei) {
    int e = blockIdx.x * blockDim.x + threadIdx.x;
    if (e < N_EDGES) {
        int dst = __ldg(&ei[N_EDGES + e]);
        atomicAdd(&g_cnt[dst], 1.0f);
    }
}

// ---------------- edge scatter: warp per edge, scalar RED (no-return) ------
__global__ void scatter_edges(const float* __restrict__ x_ext,
                              const int* __restrict__ ei, int use_h) {
    int t = blockIdx.x * blockDim.x + threadIdx.x;
    int e = t >> 5;
    int lane = t & 31;
    if (e >= N_EDGES) return;
    const float* feat = use_h ? (const float*)g_h : x_ext;
    int src = __ldg(&ei[e]);
    int dst = __ldg(&ei[N_EDGES + e]);
    float4 v = *(const float4*)(feat + (size_t)src * 128 + lane * 4);
    float* p = g_agg + (size_t)dst * 128 + lane * 4;
    atomicAdd(p + 0, v.x);   // result unused -> RED.E.ADD.F32
    atomicAdd(p + 1, v.y);
    atomicAdd(p + 2, v.z);
    atomicAdd(p + 3, v.w);
}

// ---------------- mean normalize: agg /= max(cnt, 1) ----------------
__global__ void scale_agg() {
    int t = blockIdx.x * blockDim.x + threadIdx.x;   // float4 granularity
    if (t < N_NODES * 32) {
        float c = g_cnt[t >> 5];
        float inv = (c > 1.f) ? (1.f / c) : 1.f;
        float4 v = ((float4*)g_agg)[t];
        v.x *= inv; v.y *= inv; v.z *= inv; v.w *= inv;
        ((float4*)g_agg)[t] = v;
    }
}

// ---------------- fused GEMM:  C = [agg | A2] @ B (+bias, opt. relu) -------
// LAYER==1: A2 = x (ext), B = g_B1 [256x128], C = g_h, relu
// LAYER==2: A2 = g_h,     B = g_B2 [256x64],  C = Cext (d_out), no relu
// Block tile: 128 rows x BN cols, 256 threads, 8x(4*NG) micro-tile per thread.
template <int LAYER>
__global__ void __launch_bounds__(256, 2)
gemm_fused(const float* __restrict__ A2ext, const float* __restrict__ bias,
           float* __restrict__ Cext) {
    constexpr int BN = (LAYER == 1) ? 128 : 64;
    constexpr int NG = (LAYER == 1) ? 2 : 1;     // column groups (split-halves)
    constexpr int BM = 128;
    constexpr int BK = 32;

    const float* B  = (LAYER == 1) ? g_B1 : g_B2;
    const float* A2 = (LAYER == 1) ? A2ext : (const float*)g_h;
    float*       C  = (LAYER == 1) ? g_h   : Cext;

    __shared__ float As[BK * BM];
    __shared__ float Bs[BK * BN];

    int t  = threadIdx.x;
    int tx = t & 15;
    int ty = t >> 4;
    int m0 = blockIdx.x * BM;

    float acc[8][4 * NG];
#pragma unroll
    for (int i = 0; i < 8; i++)
#pragma unroll
        for (int j = 0; j < 4 * NG; j++) acc[i][j] = 0.f;

    for (int kc = 0; kc < 256; kc += BK) {
        // ---- stage A tile (k-major in shared: As[k][m]) ----
#pragma unroll
        for (int q = 0; q < 4; q++) {
            int kq = (t >> 7) + q * 2;          // 0..7
            int k  = kq * 4;
            int m  = t & 127;
            int node = m0 + m;
            int kg = kc + k;
            float4 v = make_float4(0.f, 0.f, 0.f, 0.f);
            if (node < N_NODES) {
                const float* srcp = (kg < 128)
                    ? (g_agg + (size_t)node * 128 + kg)
                    : (A2    + (size_t)node * 128 + (kg - 128));
                v = *(const float4*)srcp;
            }
            As[(k + 0) * BM + m] = v.x;
            As[(k + 1) * BM + m] = v.y;
            As[(k + 2) * BM + m] = v.z;
            As[(k + 3) * BM + m] = v.w;
        }
        // ---- stage B tile (contiguous copy) ----
        constexpr int NB4 = BK * BN / 4 / 256;   // 4 (BN=128) or 2 (BN=64)
#pragma unroll
        for (int q = 0; q < NB4; q++) {
            int idx = t + q * 256;
            ((float4*)Bs)[idx] = ((const float4*)(B + (size_t)kc * BN))[idx];
        }
        __syncthreads();

        // ---- compute ----
#pragma unroll
        for (int k = 0; k < BK; k++) {
            float a[8];
            float4 a0 = *(const float4*)&As[k * BM + 4 * ty];
            float4 a1 = *(const float4*)&As[k * BM + 4 * ty + 64];
            a[0] = a0.x; a[1] = a0.y; a[2] = a0.z; a[3] = a0.w;
            a[4] = a1.x; a[5] = a1.y; a[6] = a1.z; a[7] = a1.w;
            float b[4 * NG];
            float4 b0 = *(const float4*)&Bs[k * BN + 4 * tx];
            b[0] = b0.x; b[1] = b0.y; b[2] = b0.z; b[3] = b0.w;
            if (NG == 2) {
                float4 b1 = *(const float4*)&Bs[k * BN + 4 * tx + 64];
                b[4] = b1.x; b[5] = b1.y; b[6] = b1.z; b[7] = b1.w;
            }
#pragma unroll
            for (int im = 0; im < 8; im++)
#pragma unroll
                for (int in = 0; in < 4 * NG; in++)
                    acc[im][in] = fmaf(a[im], b[in], acc[im][in]);
        }
        __syncthreads();
    }

    // ---- epilogue: bias (+relu for layer 1) ----
#pragma unroll
    for (int im = 0; im < 8; im++) {
        int r = m0 + 4 * ty + (im & 3) + (im >> 2) * 64;
        if (r < N_NODES) {
#pragma unroll
            for (int ng = 0; ng < NG; ng++) {
#pragma unroll
                for (int j = 0; j < 4; j++) {
                    int c = 4 * tx + j + ng * 64;
                    float v = acc[im][ng * 4 + j] + bias[c];
                    if (LAYER == 1) v = fmaxf(v, 0.f);
                    C[(size_t)r * BN + c] = v;
                }
            }
        }
    }
}

// ---------------- launcher ----------------
extern "C" void kernel_launch(void* const* d_in, const int* in_sizes, int n_in,
                              void* d_out, int out_size) {
    const float* x   = (const float*)d_in[0];
    const int*   ei  = (const int*)d_in[1];       // int32! (JAX x64 disabled)
    const float* W1l = (const float*)d_in[2];
    const float* b1l = (const float*)d_in[3];
    const float* W1r = (const float*)d_in[4];
    const float* W2l = (const float*)d_in[5];
    const float* b2l = (const float*)d_in[6];
    const float* W2r = (const float*)d_in[7];
    float* out = (float*)d_out;

    const int T = 256;
    int g_prep    = (256 * 128 + 256 * 64 + T - 1) / T;
    int g_zero    = (N_NODES * 32 + T - 1) / T;
    int g_count   = (N_EDGES + T - 1) / T;
    int g_scatter = (N_EDGES * 32 + T - 1) / T;
    int g_gemm    = (N_NODES + 127) / 128;

    // weights -> concatenated k-major B matrices
    prep_weights<<<g_prep, T>>>(W1l, W1r, W2l, W2r);

    // ---- layer 1 ----
    zero_agg_cnt<<<g_zero, T>>>(1);
    count_edges<<<g_count, T>>>(ei);
    scatter_edges<<<g_scatter, T>>>(x, ei, 0);
    scale_agg<<<g_zero, T>>>();
    gemm_fused<1><<<g_gemm, T>>>(x, b1l, nullptr);

    // ---- layer 2 (counts reused: same graph) ----
    zero_agg_cnt<<<g_zero, T>>>(0);
    scatter_edges<<<g_scatter, T>>>(nullptr, ei, 1);
    scale_agg<<<g_zero, T>>>();
    gemm_fused<2><<<g_gemm, T>>>(nullptr, b2l, out);
}

// round 4
// speedup vs baseline: 1.8012x; 1.8012x over previous
#include <cuda_runtime.h>

#define N_NODES 50000
#define N_EDGES 800000

// ---------------- scratch (no allocation allowed) ----------------
__device__ float g_agg[N_NODES * 128];   // aggregation buffer (reused both layers)
__device__ float g_h  [N_NODES * 128];   // layer-1 hidden activations
__device__ float g_cnt[N_NODES];         // in-degree counts (computed once)
__device__ float g_B1 [256 * 128];       // [W1l; W1r]^T  k-major: B1[k][o]
__device__ float g_B2 [256 * 64];        // [W2l; W2r]^T  k-major: B2[k][o]

// ---------------- weight prep: build concatenated k-major B ----------------
__global__ void prep_weights(const float* __restrict__ W1l, const float* __restrict__ W1r,
                             const float* __restrict__ W2l, const float* __restrict__ W2r) {
    int t = blockIdx.x * blockDim.x + threadIdx.x;
    if (t < 256 * 128) {
        int k = t >> 7, o = t & 127;
        g_B1[t] = (k < 128) ? W1l[o * 128 + k] : W1r[o * 128 + (k - 128)];
    }
    int t2 = t - 256 * 128;
    if (t2 >= 0 && t2 < 256 * 64) {
        int k = t2 >> 6, o = t2 & 63;
        g_B2[t2] = (k < 128) ? W2l[o * 128 + k] : W2r[o * 128 + (k - 128)];
    }
}

// ---------------- zero agg (and optionally cnt) ----------------
__global__ void zero_agg_cnt(int zero_cnt) {
    int t = blockIdx.x * blockDim.x + threadIdx.x;
    float4 z = make_float4(0.f, 0.f, 0.f, 0.f);
    if (t < N_NODES * 32) ((float4*)g_agg)[t] = z;
    if (zero_cnt && t < N_NODES) g_cnt[t] = 0.f;
}

// ---------------- degree count (once; graph identical for both layers) -----
__global__ void count_edges(const int* __restrict__ ei) {
    int e = blockIdx.x * blockDim.x + threadIdx.x;
    if (e < N_EDGES) {
        int dst = __ldg(&ei[N_EDGES + e]);
        atomicAdd(&g_cnt[dst], 1.0f);
    }
}

// ---------------- edge scatter: warp per edge, vectorized RED.128 ----------
__global__ void scatter_edges(const float* __restrict__ x_ext,
                              const int* __restrict__ ei, int use_h) {
    int t = blockIdx.x * blockDim.x + threadIdx.x;
    int e = t >> 5;
    int lane = t & 31;
    if (e >= N_EDGES) return;
    const float* feat = use_h ? (const float*)g_h : x_ext;
    int src = __ldg(&ei[e]);
    int dst = __ldg(&ei[N_EDGES + e]);
    float4 v = *(const float4*)(feat + (size_t)src * 128 + lane * 4);
    float* p = g_agg + (size_t)dst * 128 + lane * 4;
    asm volatile("red.global.add.v4.f32 [%0], {%1,%2,%3,%4};"
                 :: "l"(p), "f"(v.x), "f"(v.y), "f"(v.z), "f"(v.w) : "memory");
}

// ---------------- fused GEMM:  C = [agg/cnt | A2] @ B (+bias, opt. relu) ---
// Mean-normalization fused into the A-tile staging (first 128 k's).
// LAYER==1: A2 = x (ext), B = g_B1 [256x128], C = g_h, relu
// LAYER==2: A2 = g_h,     B = g_B2 [256x64],  C = Cext (d_out), no relu
template <int LAYER>
__global__ void __launch_bounds__(256, 2)
gemm_fused(const float* __restrict__ A2ext, const float* __restrict__ bias,
           float* __restrict__ Cext) {
    constexpr int BN = (LAYER == 1) ? 128 : 64;
    constexpr int NG = (LAYER == 1) ? 2 : 1;     // column groups (split-halves)
    constexpr int BM = 128;
    constexpr int BK = 32;

    const float* B  = (LAYER == 1) ? g_B1 : g_B2;
    const float* A2 = (LAYER == 1) ? A2ext : (const float*)g_h;
    float*       C  = (LAYER == 1) ? g_h   : Cext;

    __shared__ float As[BK * BM];
    __shared__ float Bs[BK * BN];

    int t  = threadIdx.x;
    int tx = t & 15;
    int ty = t >> 4;
    int m0 = blockIdx.x * BM;

    // per-thread staging row is fixed: m = t & 127
    int m_stage = t & 127;
    int node_stage = m0 + m_stage;
    float inv = 1.0f;
    if (node_stage < N_NODES) {
        float c = g_cnt[node_stage];
        inv = (c > 1.f) ? (1.f / c) : 1.f;
    }

    float acc[8][4 * NG];
#pragma unroll
    for (int i = 0; i < 8; i++)
#pragma unroll
        for (int j = 0; j < 4 * NG; j++) acc[i][j] = 0.f;

    for (int kc = 0; kc < 256; kc += BK) {
        // ---- stage A tile (k-major in shared: As[k][m]); fold mean scale ----
#pragma unroll
        for (int q = 0; q < 4; q++) {
            int kq = (t >> 7) + q * 2;          // 0..7
            int k  = kq * 4;
            int kg = kc + k;
            float4 v = make_float4(0.f, 0.f, 0.f, 0.f);
            if (node_stage < N_NODES) {
                if (kg < 128) {
                    v = *(const float4*)(g_agg + (size_t)node_stage * 128 + kg);
                    v.x *= inv; v.y *= inv; v.z *= inv; v.w *= inv;
                } else {
                    v = *(const float4*)(A2 + (size_t)node_stage * 128 + (kg - 128));
                }
            }
            As[(k + 0) * BM + m_stage] = v.x;
            As[(k + 1) * BM + m_stage] = v.y;
            As[(k + 2) * BM + m_stage] = v.z;
            As[(k + 3) * BM + m_stage] = v.w;
        }
        // ---- stage B tile (contiguous copy) ----
        constexpr int NB4 = BK * BN / 4 / 256;   // 4 (BN=128) or 2 (BN=64)
#pragma unroll
        for (int q = 0; q < NB4; q++) {
            int idx = t + q * 256;
            ((float4*)Bs)[idx] = ((const float4*)(B + (size_t)kc * BN))[idx];
        }
        __syncthreads();

        // ---- compute ----
#pragma unroll
        for (int k = 0; k < BK; k++) {
            float a[8];
            float4 a0 = *(const float4*)&As[k * BM + 4 * ty];
            float4 a1 = *(const float4*)&As[k * BM + 4 * ty + 64];
            a[0] = a0.x; a[1] = a0.y; a[2] = a0.z; a[3] = a0.w;
            a[4] = a1.x; a[5] = a1.y; a[6] = a1.z; a[7] = a1.w;
            float b[4 * NG];
            float4 b0 = *(const float4*)&Bs[k * BN + 4 * tx];
            b[0] = b0.x; b[1] = b0.y; b[2] = b0.z; b[3] = b0.w;
            if (NG == 2) {
                float4 b1 = *(const float4*)&Bs[k * BN + 4 * tx + 64];
                b[4] = b1.x; b[5] = b1.y; b[6] = b1.z; b[7] = b1.w;
            }
#pragma unroll
            for (int im = 0; im < 8; im++)
#pragma unroll
                for (int in = 0; in < 4 * NG; in++)
                    acc[im][in] = fmaf(a[im], b[in], acc[im][in]);
        }
        __syncthreads();
    }

    // ---- epilogue: bias (+relu for layer 1) ----
#pragma unroll
    for (int im = 0; im < 8; im++) {
        int r = m0 + 4 * ty + (im & 3) + (im >> 2) * 64;
        if (r < N_NODES) {
#pragma unroll
            for (int ng = 0; ng < NG; ng++) {
#pragma unroll
                for (int j = 0; j < 4; j++) {
                    int c = 4 * tx + j + ng * 64;
                    float v = acc[im][ng * 4 + j] + bias[c];
                    if (LAYER == 1) v = fmaxf(v, 0.f);
                    C[(size_t)r * BN + c] = v;
                }
            }
        }
    }
}

// ---------------- launcher ----------------
extern "C" void kernel_launch(void* const* d_in, const int* in_sizes, int n_in,
                              void* d_out, int out_size) {
    const float* x   = (const float*)d_in[0];
    const int*   ei  = (const int*)d_in[1];       // int32 (JAX x64 disabled)
    const float* W1l = (const float*)d_in[2];
    const float* b1l = (const float*)d_in[3];
    const float* W1r = (const float*)d_in[4];
    const float* W2l = (const float*)d_in[5];
    const float* b2l = (const float*)d_in[6];
    const float* W2r = (const float*)d_in[7];
    float* out = (float*)d_out;

    const int T = 256;
    int g_prep    = (256 * 128 + 256 * 64 + T - 1) / T;
    int g_zero    = (N_NODES * 32 + T - 1) / T;
    int g_count   = (N_EDGES + T - 1) / T;
    int g_scatter = (N_EDGES * 32 + T - 1) / T;
    int g_gemm    = (N_NODES + 127) / 128;

    // weights -> concatenated k-major B matrices
    prep_weights<<<g_prep, T>>>(W1l, W1r, W2l, W2r);

    // ---- layer 1 ----
    zero_agg_cnt<<<g_zero, T>>>(1);
    count_edges<<<g_count, T>>>(ei);
    scatter_edges<<<g_scatter, T>>>(x, ei, 0);
    gemm_fused<1><<<g_gemm, T>>>(x, b1l, nullptr);

    // ---- layer 2 (counts reused: same graph) ----
    zero_agg_cnt<<<g_zero, T>>>(0);
    scatter_edges<<<g_scatter, T>>>(nullptr, ei, 1);
    gemm_fused<2><<<g_gemm, T>>>(nullptr, b2l, out);
}